// round 2
// baseline (speedup 1.0000x reference)
#include <cuda_runtime.h>

// Reference semantics (note: the reference's reshape SCRAMBLES (Ci, D0p)):
//   out[b,o,d0,p1,p2,p3] = bias[o]
//     + sum_{i=0..2, c=0..31, k1,k2,k3} w[i,o,c,k1,k2,k3] * xp[b, L/26, L%26, p1+k1, p2+k2, p3+k3]
//   where L = (d0+i)*32 + c, and xp is x zero-padded by 1 on all four spatial dims.
// Shapes: x(2,32,24,24,24,24) f32, w(3,64,32,3,3,3) f32, bias(64) f32, out(2,64,24,24,24,24) f32.

#define CI 32
#define CO 64
#define DDIM 24
#define OC_PER_BLOCK 16
#define OC_PER_THREAD 4

__global__ __launch_bounds__(256, 2)
void conv4d_kernel(const float* __restrict__ x,
                   const float* __restrict__ w,
                   const float* __restrict__ bias,
                   float* __restrict__ out)
{
    __shared__ float xs[26 * 26];               // zero-padded input plane
    __shared__ float ws[OC_PER_BLOCK * 9];      // 16 oc x (k2,k3)

    const int blk = blockIdx.x;                 // b*576 + d0*24 + d1
    const int d1  = blk % DDIM;
    const int t0  = blk / DDIM;
    const int d0  = t0 % DDIM;
    const int b   = t0 / DDIM;
    const int oc0 = blockIdx.y * OC_PER_BLOCK;

    const int tid = threadIdx.x;
    const int tx  = tid & 63;   // position group 0..63
    const int ty  = tid >> 6;   // channel subgroup 0..3
    const int rb  = tx >> 3;    // d2 block 0..7 (rows rb*3..rb*3+2)
    const int cb  = tx & 7;     // d3 block 0..7 (cols cb*3..cb*3+2)

    float acc[OC_PER_THREAD][3][3];
    #pragma unroll
    for (int c = 0; c < OC_PER_THREAD; c++)
        #pragma unroll
        for (int i = 0; i < 3; i++)
            #pragma unroll
            for (int j = 0; j < 3; j++)
                acc[c][i][j] = 0.0f;

    for (int i = 0; i < 3; i++) {               // outermost kernel tap
        for (int c = 0; c < CI; c++) {          // weight channel (frame-conv channel)
            // scrambled source: L = (d0+i)*32 + c -> (ci', padded frame d0p')
            const int L   = (d0 + i) * CI + c;
            const int cin = L / 26;             // source input channel
            const int e0  = (L % 26) - 1;       // unpadded source frame
            if ((unsigned)e0 >= (unsigned)DDIM) continue;  // zero-padded frame

            for (int k1 = 0; k1 < 3; k1++) {
                const int e1 = d1 + k1 - 1;
                if ((unsigned)e1 >= (unsigned)DDIM) continue;

                // ---- stage input plane x[b,cin,e0,e1,:,:] into padded smem ----
                const float* xp = x + ((((size_t)b * CI + cin) * DDIM + e0) * DDIM + e1) * 576;
                for (int idx = tid; idx < 676; idx += 256) {
                    const int r  = idx / 26;
                    const int c_ = idx - r * 26;
                    const int p2 = r - 1;
                    const int p3 = c_ - 1;
                    float v = 0.0f;
                    if ((unsigned)p2 < (unsigned)DDIM && (unsigned)p3 < (unsigned)DDIM)
                        v = xp[p2 * DDIM + p3];
                    xs[idx] = v;
                }
                // ---- stage weights w[i, oc0+ocl, c, k1, k2, k3] ----
                if (tid < OC_PER_BLOCK * 9) {
                    const int ocl = tid / 9;
                    const int t   = tid - ocl * 9;   // k2*3+k3
                    ws[tid] = w[(((size_t)i * CO + oc0 + ocl) * CI + c) * 27 + k1 * 9 + t];
                }
                __syncthreads();

                // ---- register-load 5x5 input patch ----
                float xr[5][5];
                #pragma unroll
                for (int ii = 0; ii < 5; ii++)
                    #pragma unroll
                    for (int jj = 0; jj < 5; jj++)
                        xr[ii][jj] = xs[(rb * 3 + ii) * 26 + cb * 3 + jj];

                // ---- outer-product FMAs: 4 oc x 9 taps x 9 positions = 324 ----
                #pragma unroll
                for (int cc = 0; cc < OC_PER_THREAD; cc++) {
                    const int ocl = ty * OC_PER_THREAD + cc;
                    #pragma unroll
                    for (int k2 = 0; k2 < 3; k2++) {
                        #pragma unroll
                        for (int k3 = 0; k3 < 3; k3++) {
                            const float wv = ws[ocl * 9 + k2 * 3 + k3];
                            #pragma unroll
                            for (int ii = 0; ii < 3; ii++)
                                #pragma unroll
                                for (int jj = 0; jj < 3; jj++)
                                    acc[cc][ii][jj] += xr[ii + k2][jj + k3] * wv;
                        }
                    }
                }
                __syncthreads();
            }
        }
    }

    // ---- epilogue: add bias, write out ----
    #pragma unroll
    for (int cc = 0; cc < OC_PER_THREAD; cc++) {
        const int oc = oc0 + ty * OC_PER_THREAD + cc;
        const float bv = bias[oc];
        const size_t obase = (((size_t)b * CO + oc) * 576 + (size_t)d0 * DDIM + d1) * 576;
        #pragma unroll
        for (int ii = 0; ii < 3; ii++) {
            const int p2 = rb * 3 + ii;
            #pragma unroll
            for (int jj = 0; jj < 3; jj++) {
                const int p3 = cb * 3 + jj;
                out[obase + p2 * DDIM + p3] = acc[cc][ii][jj] + bv;
            }
        }
    }
}

extern "C" void kernel_launch(void* const* d_in, const int* in_sizes, int n_in,
                              void* d_out, int out_size)
{
    // Identify inputs by element count (robust to metadata ordering):
    // x: 21233664, w: 165888, bias: 64
    const float* x = nullptr;
    const float* w = nullptr;
    const float* bias = nullptr;
    for (int k = 0; k < n_in; k++) {
        if (in_sizes[k] == 2 * 32 * 24 * 24 * 24 * 24) x    = (const float*)d_in[k];
        else if (in_sizes[k] == 3 * 64 * 32 * 27)      w    = (const float*)d_in[k];
        else if (in_sizes[k] == 64)                    bias = (const float*)d_in[k];
    }
    float* out = (float*)d_out;                 // (2,64,24,24,24,24)

    dim3 grid(2 * 24 * 24, CO / OC_PER_BLOCK);  // (1152, 4)
    dim3 block(256);
    conv4d_kernel<<<grid, block>>>(x, w, bias, out);
}

// round 3
// speedup vs baseline: 1.9037x; 1.9037x over previous
#include <cuda_runtime.h>

// out[b,o,d0,p1,p2,p3] = bias[o]
//   + sum_{i,c,k1,k2,k3} w[i,o,c,k1,k2,k3] * xp[b, L/26, L%26, p1+k1, p2+k2, p3+k3],  L=(d0+i)*32+c
// xp = x zero-padded by 1 on all four spatial dims (reference's reshape scrambles (Ci,D0p)).
// x(2,32,24,24,24,24) f32, w(3,64,32,3,3,3) f32, bias(64) f32, out(2,64,24,24,24,24) f32.

#define DDIM 24
#define CI 32
#define CO 64
#define OCB 16
#define NITER 96

typedef unsigned long long u64;

__device__ __forceinline__ u64 pack_dup(float a) {
    u64 r;
    unsigned ai = __float_as_uint(a);
    asm("mov.b64 %0, {%1, %1};" : "=l"(r) : "r"(ai));
    return r;
}
__device__ __forceinline__ void fma2(u64 &acc, u64 x, u64 wv) {
    asm("fma.rn.f32x2 %0, %1, %2, %0;" : "+l"(acc) : "l"(x), "l"(wv));
}
__device__ __forceinline__ void unpack2(u64 v, float &lo, float &hi) {
    unsigned l, h;
    asm("mov.b64 {%0, %1}, %2;" : "=r"(l), "=r"(h) : "l"(v));
    lo = __uint_as_float(l); hi = __uint_as_float(h);
}

__global__ __launch_bounds__(256, 2)
void conv4d_kernel(const float* __restrict__ x,
                   const float* __restrict__ w,
                   const float* __restrict__ bias,
                   float* __restrict__ out)
{
    __shared__ float  xv[2][3 * 676];    // 3 zero-padded 26x26 slices (k1 = 0..2)
    __shared__ float2 wv2[2][8 * 27];    // 8 oc-pairs x 27 taps

    const int blk = blockIdx.x;          // b*576 + d0*24 + d1
    const int d1  = blk % DDIM;
    const int t0  = blk / DDIM;
    const int d0  = t0 % DDIM;
    const int b   = t0 / DDIM;
    const int oc0 = blockIdx.y * OCB;

    const int tid = threadIdx.x;
    const int tx  = tid & 63;
    const int ty  = tid >> 6;
    const int rb  = tx >> 3;             // d2 block (rows rb*3..rb*3+2)
    const int cb  = tx & 7;              // d3 block (cols cb*3..cb*3+2)

    // ---- loop-invariant staging metadata (hoisted div/mod) ----
    int xoff[8]; unsigned xmask = 0;
    #pragma unroll
    for (int k = 0; k < 8; k++) {
        const int idx = tid + k * 256;
        const int s   = idx / 676, rem = idx - s * 676;
        const int r   = rem / 26,  c_  = rem - r * 26;
        const int e1  = d1 + s - 1, p2 = r - 1, p3 = c_ - 1;
        const bool ok = (idx < 2028) && (unsigned)e1 < DDIM &&
                        (unsigned)p2 < DDIM && (unsigned)p3 < DDIM;
        xoff[k] = e1 * 576 + p2 * 24 + p3;
        if (ok) xmask |= 1u << k;
    }
    int wgoff[2], wsts[2]; unsigned wok = 0;
    #pragma unroll
    for (int k = 0; k < 2; k++) {
        const int e = tid + k * 256;
        const int ocl = e / 27, t = e - ocl * 27;
        if (e < 432) wok |= 1u << k;
        wgoff[k] = (oc0 + ocl) * (CI * 27) + t;               // + i*55296 + c*27
        wsts[k]  = (ocl >> 1) * 54 + t * 2 + (ocl & 1);       // float index into wv2 row
    }

    u64 acc2[2][9];
    #pragma unroll
    for (int p = 0; p < 2; p++)
        #pragma unroll
        for (int q = 0; q < 9; q++) acc2[p][q] = 0ull;

    const int L0 = d0 * 32;

    // ---- stage L0 (i=0, c=0 since L0 % 32 == 0) ----
    {
        const int cin = L0 / 26, e0p = L0 % 26;
        const bool e0ok = (unsigned)(e0p - 1) < DDIM;
        const float* xrow = x + ((size_t)(b * CI + cin) * DDIM + (e0p - 1)) * 13824;
        float xr[8], wr[2];
        #pragma unroll
        for (int k = 0; k < 8; k++)
            xr[k] = (e0ok && ((xmask >> k) & 1)) ? __ldg(xrow + xoff[k]) : 0.0f;
        const float* wb = w + 0 * 55296 + 0 * 27;
        #pragma unroll
        for (int k = 0; k < 2; k++)
            wr[k] = ((wok >> k) & 1) ? __ldg(wb + wgoff[k]) : 0.0f;
        #pragma unroll
        for (int k = 0; k < 8; k++) {
            const int idx = tid + k * 256;
            if (idx < 2028) xv[0][idx] = xr[k];
        }
        float* wf = (float*)wv2[0];
        #pragma unroll
        for (int k = 0; k < 2; k++)
            if ((wok >> k) & 1) wf[wsts[k]] = wr[k];
    }
    __syncthreads();

    int pb = 0;
    int ccin = L0 / 26, ce0p = L0 % 26;       // (cin, L%26) for CURRENT L
    for (int Lk = 0; Lk < NITER; Lk++) {
        const bool have_next = (Lk < NITER - 1);

        // ---- prefetch stage for L+1 into registers ----
        int ncin = ccin, ne0p = ce0p + 1;
        if (ne0p == 26) { ne0p = 0; ncin++; }
        float xr[8], wr[2];
        if (have_next) {
            const bool ne0ok = (unsigned)(ne0p - 1) < DDIM;
            const float* xrow = x + ((size_t)(b * CI + ncin) * DDIM + (ne0p - 1)) * 13824;
            #pragma unroll
            for (int k = 0; k < 8; k++)
                xr[k] = (ne0ok && ((xmask >> k) & 1)) ? __ldg(xrow + xoff[k]) : 0.0f;
            const int i_n = (Lk + 1) >> 5;               // (L+1)/32 - d0
            const int c_n = (L0 + Lk + 1) & 31;
            const float* wb = w + i_n * 55296 + c_n * 27;
            #pragma unroll
            for (int k = 0; k < 2; k++)
                wr[k] = ((wok >> k) & 1) ? __ldg(wb + wgoff[k]) : 0.0f;
        }

        // ---- compute current L from buffer pb ----
        if ((unsigned)(ce0p - 1) < DDIM) {
            #pragma unroll
            for (int k1 = 0; k1 < 3; k1++) {
                u64 wp0[9], wp1[9];
                const u64* wr0 = (const u64*)&wv2[pb][(ty * 2 + 0) * 27 + k1 * 9];
                const u64* wr1 = (const u64*)&wv2[pb][(ty * 2 + 1) * 27 + k1 * 9];
                #pragma unroll
                for (int t = 0; t < 9; t++) { wp0[t] = wr0[t]; wp1[t] = wr1[t]; }

                const float* xsl = &xv[pb][k1 * 676 + rb * 78 + cb * 3];
                #pragma unroll
                for (int r = 0; r < 5; r++) {
                    #pragma unroll
                    for (int s = 0; s < 5; s++) {
                        const u64 x2 = pack_dup(xsl[r * 26 + s]);
                        #pragma unroll
                        for (int k2 = (r > 2 ? r - 2 : 0); k2 <= (r < 2 ? r : 2); k2++) {
                            #pragma unroll
                            for (int k3 = (s > 2 ? s - 2 : 0); k3 <= (s < 2 ? s : 2); k3++) {
                                const int pos = (r - k2) * 3 + (s - k3);
                                const int t   = k2 * 3 + k3;
                                fma2(acc2[0][pos], x2, wp0[t]);
                                fma2(acc2[1][pos], x2, wp1[t]);
                            }
                        }
                    }
                }
            }
        }

        // ---- commit prefetched stage, flip ----
        if (have_next) {
            #pragma unroll
            for (int k = 0; k < 8; k++) {
                const int idx = tid + k * 256;
                if (idx < 2028) xv[pb ^ 1][idx] = xr[k];
            }
            float* wf = (float*)wv2[pb ^ 1];
            #pragma unroll
            for (int k = 0; k < 2; k++)
                if ((wok >> k) & 1) wf[wsts[k]] = wr[k];
            __syncthreads();
        }
        pb ^= 1;
        ccin = ncin; ce0p = ne0p;
    }

    // ---- epilogue: unpack, add bias, store ----
    #pragma unroll
    for (int p = 0; p < 2; p++) {
        const int oce = oc0 + ty * 4 + p * 2;       // even oc of the pair
        const float bv0 = bias[oce];
        const float bv1 = bias[oce + 1];
        const size_t ob0 = ((size_t)(b * CO + oce) * 576 + d0 * 24 + d1) * 576;
        const size_t ob1 = ob0 + (size_t)331776;    // next oc: +576*576
        #pragma unroll
        for (int ii = 0; ii < 3; ii++) {
            #pragma unroll
            for (int jj = 0; jj < 3; jj++) {
                float lo, hi;
                unpack2(acc2[p][ii * 3 + jj], lo, hi);
                const int po = (rb * 3 + ii) * 24 + cb * 3 + jj;
                out[ob0 + po] = lo + bv0;
                out[ob1 + po] = hi + bv1;
            }
        }
    }
}

extern "C" void kernel_launch(void* const* d_in, const int* in_sizes, int n_in,
                              void* d_out, int out_size)
{
    const float* x = nullptr;
    const float* w = nullptr;
    const float* bias = nullptr;
    for (int k = 0; k < n_in; k++) {
        if (in_sizes[k] == 2 * 32 * 24 * 24 * 24 * 24) x    = (const float*)d_in[k];
        else if (in_sizes[k] == 3 * 64 * 32 * 27)      w    = (const float*)d_in[k];
        else if (in_sizes[k] == 64)                    bias = (const float*)d_in[k];
    }
    float* out = (float*)d_out;

    dim3 grid(2 * 24 * 24, CO / OCB);   // (1152, 4)
    dim3 block(256);
    conv4d_kernel<<<grid, block>>>(x, w, bias, out);
}